// round 3
// baseline (speedup 1.0000x reference)
#include <cuda_runtime.h>

#define CH 64
#define MMAX 50000

// Scratch (allocation-free). float4 type => guaranteed 16B alignment for
// vector RED / vector loads.
__device__ float4 g_S4[MMAX * (CH / 4)];
__device__ float  g_deg[MMAX];

__global__ void zero_kernel(int M) {
    int i = blockIdx.x * blockDim.x + threadIdx.x;
    int total = M * (CH / 4);
    if (i < total) g_S4[i] = make_float4(0.f, 0.f, 0.f, 0.f);
    if (i < M) g_deg[i] = 0.0f;
}

// One edge handled by 16 threads; each thread moves one float4 (16B) of the
// 256B source row. Vector RED (sm_90+) keeps RED lane count at 16/edge.
__global__ void edge_kernel(const float4* __restrict__ A4,
                            const int* __restrict__ idx,
                            const int* __restrict__ idx1,
                            const float* __restrict__ ew,
                            int E) {
    int t = blockIdx.x * blockDim.x + threadIdx.x;
    int e = t >> 4;
    if (e >= E) return;
    int q = t & 15;
    int src = idx[e];
    int dst = idx1[e];
    float4 v = __ldg(&A4[src * 16 + q]);
    float4* p = &g_S4[dst * 16 + q];
    asm volatile("red.global.add.v4.f32 [%0], {%1,%2,%3,%4};"
                 :: "l"(p), "f"(v.x), "f"(v.y), "f"(v.z), "f"(v.w)
                 : "memory");
    if (q == 0) {
        atomicAdd(&g_deg[dst], __ldg(&ew[e]));
    }
}

// Epilogue: out[m,c] = deg[m]*(x·W1[c,:] + b1[c]) + S[m,:]·weight[:,c]
//                      + x·W2[c,:] + b2[c],  x = A[valid_nodes[m],:]
// Block = 256 threads = 4 row-groups x 64 cols; each thread does 4 rows, 1 col.
// W1/W2 transposed into smem so the k-loop reads are conflict-free; 4-row
// register blocking amortizes each smem weight load over 4 FMAs.
__global__ __launch_bounds__(256) void final_kernel(
        const float* __restrict__ A,
        const int* __restrict__ vn,
        const float* __restrict__ W1,
        const float* __restrict__ b1,
        const float* __restrict__ W2,
        const float* __restrict__ b2,
        const float* __restrict__ Wt,   // weight, layout [k][c]
        float* __restrict__ out,
        int M) {
    __shared__ float sW1[CH * CH];   // transposed: [k][c]
    __shared__ float sW2[CH * CH];   // transposed: [k][c]
    __shared__ float sW [CH * CH];   // weight already [k][c]

    int tid = threadIdx.x;
    for (int i = tid; i < CH * CH; i += 256) {
        int c = i >> 6, k = i & 63;          // W1/W2 are [c][k]
        sW1[k * CH + c] = W1[i];
        sW2[k * CH + c] = W2[i];
        sW[i] = Wt[i];
    }

    int c  = tid & 63;
    int g  = tid >> 6;
    float b1c = __ldg(&b1[c]);
    float b2c = __ldg(&b2[c]);
    __syncthreads();

    int m0 = blockIdx.x * 16 + g * 4;
    if (m0 >= M) return;

    const float4* A4 = (const float4*)A;

    int row[4];
    bool ok[4];
    #pragma unroll
    for (int r = 0; r < 4; r++) {
        ok[r] = (m0 + r) < M;
        row[r] = ok[r] ? vn[m0 + r] : 0;
    }

    float s1[4] = {0.f, 0.f, 0.f, 0.f};
    float s2[4] = {0.f, 0.f, 0.f, 0.f};
    float s3[4] = {0.f, 0.f, 0.f, 0.f};

    #pragma unroll
    for (int kk = 0; kk < 16; kk++) {
        float w1v[4], w2v[4], wv[4];
        #pragma unroll
        for (int j = 0; j < 4; j++) {
            int k = kk * 4 + j;
            w1v[j] = sW1[k * CH + c];
            w2v[j] = sW2[k * CH + c];
            wv[j]  = sW [k * CH + c];
        }
        #pragma unroll
        for (int r = 0; r < 4; r++) {
            float4 x = __ldg(&A4[row[r] * 16 + kk]);
            float4 s = g_S4[(m0 + r) * 16 + kk];
            s1[r] += x.x * w1v[0] + x.y * w1v[1] + x.z * w1v[2] + x.w * w1v[3];
            s2[r] += x.x * w2v[0] + x.y * w2v[1] + x.z * w2v[2] + x.w * w2v[3];
            s3[r] += s.x * wv[0]  + s.y * wv[1]  + s.z * wv[2]  + s.w * wv[3];
        }
    }

    #pragma unroll
    for (int r = 0; r < 4; r++) {
        if (ok[r]) {
            float d = g_deg[m0 + r];
            out[(m0 + r) * CH + c] =
                d * (s1[r] + b1c) + s3[r] + s2[r] + b2c;
        }
    }
}

extern "C" void kernel_launch(void* const* d_in, const int* in_sizes, int n_in,
                              void* d_out, int out_size) {
    const float* A    = (const float*)d_in[0];   // [N, 64] f32
    const int*   vn   = (const int*)d_in[1];     // [M] int32 (JAX x64 disabled)
    const int*   idx  = (const int*)d_in[2];     // [E] int32
    const int*   idx1 = (const int*)d_in[3];     // [E] int32
    const float* ew   = (const float*)d_in[4];   // [E] f32
    const float* Wt   = (const float*)d_in[5];   // [64, 64] = [CIN][COUT]
    const float* W1   = (const float*)d_in[6];   // [64, 64] = [COUT][CIN]
    const float* b1   = (const float*)d_in[7];   // [64]
    const float* W2   = (const float*)d_in[8];   // [64, 64]
    const float* b2   = (const float*)d_in[9];   // [64]
    float* out = (float*)d_out;

    int M = in_sizes[1];
    int E = in_sizes[2];

    {
        int total = M * (CH / 4);
        int blocks = (total + 255) / 256;
        zero_kernel<<<blocks, 256>>>(M);
    }
    {
        long long threads = (long long)E * 16;
        int blocks = (int)((threads + 255) / 256);
        edge_kernel<<<blocks, 256>>>((const float4*)A, idx, idx1, ew, E);
    }
    {
        int blocks = (M + 15) / 16;
        final_kernel<<<blocks, 256>>>(A, vn, W1, b1, W2, b2, Wt, out, M);
    }
}